// round 15
// baseline (speedup 1.0000x reference)
#include <cuda_runtime.h>
#include <math.h>

// ---------------- scratch ----------------
#define BMAX 4096
__device__ __align__(16) float d_g[BMAX * 16];
__device__ __align__(16) float d_q[BMAX * 16];
__device__ __align__(16) float d_k[BMAX * 16];   // pre-scaled by softmax scale
__device__ __align__(16) float d_outpre[BMAX * 2];
__device__ __align__(16) float d_ps[BMAX * 8];        // partial softmax denominators
__device__ __align__(16) float d_pacc[BMAX * 8 * 16]; // partial numerators

// ---------------- packed f32x2 helpers ----------------
typedef unsigned long long u64;
__device__ __forceinline__ u64 pk(float lo, float hi) {
    u64 r; asm("mov.b64 %0, {%1,%2};" : "=l"(r) : "f"(lo), "f"(hi)); return r;
}
__device__ __forceinline__ u64 pk1(float v) { return pk(v, v); }
__device__ __forceinline__ u64 fma2(u64 a, u64 b, u64 c) {
    u64 d; asm("fma.rn.f32x2 %0, %1, %2, %3;" : "=l"(d) : "l"(a), "l"(b), "l"(c)); return d;
}
__device__ __forceinline__ u64 add2(u64 a, u64 b) {
    u64 d; asm("add.rn.f32x2 %0, %1, %2;" : "=l"(d) : "l"(a), "l"(b)); return d;
}
__device__ __forceinline__ float2 up2(u64 v) {
    float2 f; asm("mov.b64 {%0,%1}, %2;" : "=f"(f.x), "=f"(f.y) : "l"(v)); return f;
}
// straddle pair: (hi of a, lo of b) — register-only
__device__ __forceinline__ u64 pkmid(u64 a, u64 b) {
    float2 fa = up2(a), fb = up2(b);
    return pk(fa.y, fb.x);
}

// ---------------- fused feature kernel smem layout (floats) — R11 layout ----------------
#define O_WC1   0
#define O_BS1   96
#define O_WC2   104
#define O_BS2   1640
#define O_WC3   1656
#define O_BS3   7800
#define O_A     7832
#define O_IMG   O_A
#define O_H2    O_A
#define O_H1    9752
#define O_W1    9752
#define O_W2    10808
#define O_R     11336
#define O_FEAT  11352
#define O_AVEC  11384
#define O_GVEC  11416
#define SM_FLOATS 12632
#define SM_BYTES  (SM_FLOATS * 4)

__global__ void __launch_bounds__(256, 4) k_feat(
    const float* __restrict__ x,
    const float* __restrict__ c1w, const float* __restrict__ c1b,
    const float* __restrict__ c2w, const float* __restrict__ c2b,
    const float* __restrict__ c3w, const float* __restrict__ c3b,
    const float* __restrict__ w1, const float* __restrict__ w2,
    const float* __restrict__ R, const float* __restrict__ ent)
{
    extern __shared__ __align__(16) float sm[];
    float* wc1 = sm + O_WC1;  float* bs1 = sm + O_BS1;
    float* wc2 = sm + O_WC2;  float* bs2 = sm + O_BS2;
    float* wc3 = sm + O_WC3;  float* bs3 = sm + O_BS3;
    float* img = sm + O_IMG;  float* h1 = sm + O_H1;  float* h2 = sm + O_H2;

    int b = blockIdx.x, t = threadIdx.x;

    {
        float4 z = make_float4(0.f, 0.f, 0.f, 0.f);
        float4* p1 = (float4*)img;
        float4* p2 = (float4*)h1;
        for (int i = t; i < 306; i += 256) p1[i] = z;
        for (int i = t; i < 720; i += 256) p2[i] = z;
    }
    for (int i = t; i < 72; i += 256)   { int g = i / 9, zz = i - g * 9; wc1[g * 12 + zz] = c1w[i]; }
    if (t < 8)  bs1[t] = c1b[t];
    for (int i = t; i < 1152; i += 256) { int g = i / 9, zz = i - g * 9; wc2[g * 12 + zz] = c2w[i]; }
    if (t < 16) bs2[t] = c2b[t];
    for (int i = t; i < 4608; i += 256) { int g = i / 9, zz = i - g * 9; wc3[g * 12 + zz] = c3w[i]; }
    if (t < 32) bs3[t] = c3b[t];
    __syncthreads();

    {
        float4 v = ((const float4*)x)[b * 256 + t];
        int r = t >> 3, c = (t & 7) * 4;
        float* dst = img + (r + 1) * 36 + c + 1;
        dst[0] = v.x; dst[1] = v.y; dst[2] = v.z; dst[3] = v.w;
    }
    __syncthreads();

    // ---- conv1 ----
    {
        int ph = t >> 4, pw = t & 15;
        const float* ip = img + 2 * ph * 36 + 2 * pw;   // even col -> 8B aligned
        u64 pr[4][3];
#pragma unroll
        for (int yy = 0; yy < 4; yy++) {
            u64 a01 = *(const u64*)(ip + yy * 36);
            u64 a23 = *(const u64*)(ip + yy * 36 + 2);
            pr[yy][0] = a01;
            pr[yy][1] = pkmid(a01, a23);
            pr[yy][2] = a23;
        }
#pragma unroll
        for (int c = 0; c < 8; c++) {
            const float4* wp4 = (const float4*)(wc1 + c * 12);
            float4 wa = wp4[0], wb = wp4[1];
            float w8 = ((const float*)wp4)[8];
            float wv[9] = { wa.x, wa.y, wa.z, wa.w, wb.x, wb.y, wb.z, wb.w, w8 };
            u64 aA = pk1(bs1[c]), aB = aA;
#pragma unroll
            for (int ky = 0; ky < 3; ky++)
#pragma unroll
                for (int kx = 0; kx < 3; kx++) {
                    u64 w2v = pk1(wv[ky * 3 + kx]);
                    aA = fma2(pr[ky][kx], w2v, aA);
                    aB = fma2(pr[ky + 1][kx], w2v, aB);
                }
            float2 A = up2(aA), Bv = up2(aB);
            float m = fmaxf(fmaxf(fmaxf(A.x, A.y), fmaxf(Bv.x, Bv.y)), 0.f);
            h1[c * 360 + (ph + 1) * 20 + (pw + 1)] = m;
        }
    }
    __syncthreads();

    {
        float4 z = make_float4(0.f, 0.f, 0.f, 0.f);
        float4* p3 = (float4*)h2;
        for (int i = t; i < 480; i += 256) p3[i] = z;
    }
    __syncthreads();

    // ---- conv2 ----
    {
        int c0 = t >> 6, pos = t & 63, ph = pos >> 3, pw = pos & 7;
        u64 accA[4], accB[4];
#pragma unroll
        for (int oo = 0; oo < 4; oo++) { accA[oo] = pk1(bs2[c0 + 4 * oo]); accB[oo] = accA[oo]; }
#pragma unroll 2
        for (int ic = 0; ic < 8; ic++) {
            const float* hp = h1 + ic * 360 + 2 * ph * 20 + 2 * pw;  // even col -> 8B aligned
            u64 pr[4][3];
#pragma unroll
            for (int yy = 0; yy < 4; yy++) {
                u64 a01 = *(const u64*)(hp + yy * 20);
                u64 a23 = *(const u64*)(hp + yy * 20 + 2);
                pr[yy][0] = a01;
                pr[yy][1] = pkmid(a01, a23);
                pr[yy][2] = a23;
            }
#pragma unroll
            for (int oo = 0; oo < 4; oo++) {
                const float4* wp4 = (const float4*)(wc2 + ((c0 + 4 * oo) * 8 + ic) * 12);
                float4 wa = wp4[0], wb = wp4[1];
                float w8 = ((const float*)wp4)[8];
                float wv[9] = { wa.x, wa.y, wa.z, wa.w, wb.x, wb.y, wb.z, wb.w, w8 };
#pragma unroll
                for (int ky = 0; ky < 3; ky++)
#pragma unroll
                    for (int kx = 0; kx < 3; kx++) {
                        u64 w2v = pk1(wv[ky * 3 + kx]);
                        accA[oo] = fma2(pr[ky][kx], w2v, accA[oo]);
                        accB[oo] = fma2(pr[ky + 1][kx], w2v, accB[oo]);
                    }
            }
        }
#pragma unroll
        for (int oo = 0; oo < 4; oo++) {
            float2 A = up2(accA[oo]), Bv = up2(accB[oo]);
            float m = fmaxf(fmaxf(fmaxf(A.x, A.y), fmaxf(Bv.x, Bv.y)), 0.f);
            h2[(c0 + 4 * oo) * 120 + (ph + 1) * 12 + (pw + 1)] = m;
        }
    }
    __syncthreads();

    // ---- conv3 + mean; stage gnn weights into dead h1 region ----
    float* w1s = sm + O_W1; float* w2s = sm + O_W2; float* Rs = sm + O_R;
    float* feats = sm + O_FEAT; float* avec = sm + O_AVEC; float* gvec = sm + O_GVEC;
    for (int i = t; i < 1024; i += 256) w1s[(i >> 5) * 33 + (i & 31)] = w1[i];
    for (int i = t; i < 512; i += 256)  w2s[(i >> 5) * 33 + (i & 31)] = w2[i];
    if (t < 16) Rs[t] = R[t];
    {
        int oc = t >> 3, oy = t & 7;
        u64 acc[4];
#pragma unroll
        for (int m = 0; m < 4; m++) acc[m] = pk1(bs3[oc]);
#pragma unroll 2
        for (int ic = 0; ic < 16; ic++) {
            const ulonglong2* rpu = (const ulonglong2*)(h2 + ic * 120 + oy * 12);  // 16B aligned
            const float4* wp4 = (const float4*)(wc3 + (oc * 16 + ic) * 12);
            float4 wa = wp4[0], wb = wp4[1];
            float w8 = ((const float*)wp4)[8];
            float wv[9] = { wa.x, wa.y, wa.z, wa.w, wb.x, wb.y, wb.z, wb.w, w8 };
#pragma unroll
            for (int ky = 0; ky < 3; ky++) {
                ulonglong2 A = rpu[ky * 3], Bv = rpu[ky * 3 + 1], C = rpu[ky * 3 + 2];
                u64 pr[9];
                pr[0] = A.x;  pr[2] = A.y;  pr[4] = Bv.x;  pr[6] = Bv.y;  pr[8] = C.x;
                pr[1] = pkmid(A.x, A.y);
                pr[3] = pkmid(A.y, Bv.x);
                pr[5] = pkmid(Bv.x, Bv.y);
                pr[7] = pkmid(Bv.y, C.x);
#pragma unroll
                for (int kx = 0; kx < 3; kx++) {
                    u64 w2v = pk1(wv[ky * 3 + kx]);
                    acc[0] = fma2(pr[kx], w2v, acc[0]);
                    acc[1] = fma2(pr[2 + kx], w2v, acc[1]);
                    acc[2] = fma2(pr[4 + kx], w2v, acc[2]);
                    acc[3] = fma2(pr[6 + kx], w2v, acc[3]);
                }
            }
        }
        float s = 0.f;
#pragma unroll
        for (int m = 0; m < 4; m++) {
            float2 v = up2(acc[m]);
            s += fmaxf(v.x, 0.f) + fmaxf(v.y, 0.f);
        }
        int sub = t & 7;
#pragma unroll
        for (int off = 4; off; off >>= 1) {
            float o = __shfl_down_sync(0xffffffffu, s, off, 8);
            if (sub + off < 8) s += o;
        }
        if (sub == 0) feats[oc] = s * (1.f / 64.f);
    }
    __syncthreads();

    // ---- gnn on warp 0 ----
    if (t < 32) {
        float a = 0.f;
#pragma unroll
        for (int i = 0; i < 32; i++) a += feats[i] * w1s[t * 33 + i];
        avec[t] = tanhf(a);
        __syncwarp();
        if (t < 16) {
            float g = 0.f;
#pragma unroll
            for (int i = 0; i < 32; i++) g += avec[i] * w2s[t * 33 + i];
            g = tanhf(g);
            gvec[t] = g;
            d_g[b * 16 + t] = g;
        }
        __syncwarp();
        if (t < 16) {
            float scale = (cosf(ent[0]) + cosf(ent[1]) + cosf(ent[2])) * (1.f / 3.f) * 0.25f;
            int r = t >> 2, cc = t & 3;
            float qv = 0.f, kv = 0.f;
#pragma unroll
            for (int m = 0; m < 4; m++) {
                float gm = gvec[r * 4 + m];
                qv += gm * Rs[m * 4 + cc];
                kv += gm * Rs[cc * 4 + m];
            }
            d_q[b * 16 + t] = qv;
            d_k[b * 16 + t] = kv * scale;
        }
    }
}

// ---------------- attention partials: 16 rows x B/8 j-chunk per block ----------------
__global__ void __launch_bounds__(256) k_attn(
    const float* __restrict__ R, const float* __restrict__ ent, int B)
{
    __shared__ __align__(16) float4 ktS[256 * 5];
    __shared__ __align__(16) float4 gtS[256 * 5];
    int t = threadIdx.x;
    int r = t >> 4, part = t & 15;
    int rb = blockIdx.x >> 3;
    int chunk = blockIdx.x & 7;
    int row0 = rb * 16 + r;
    int row = min(row0, B - 1);
    int jc = B >> 3;
    int jbeg = chunk * jc;

    float temp = (cosf(ent[0]) + cosf(ent[1]) + cosf(ent[2])) * (1.f / 3.f);
    float scale = temp * 0.25f;
    float sum2 = 0.f;
#pragma unroll
    for (int c = 0; c < 4; c++) {
        float rs = fabsf(R[c * 4]) + fabsf(R[c * 4 + 1]) + fabsf(R[c * 4 + 2]) + fabsf(R[c * 4 + 3]);
        sum2 += rs * rs;
    }
    float kb = 2.f * sqrtf(sum2);

    const float4* q4 = (const float4*)d_q + row * 4;
    float4 q0 = q4[0], q1 = q4[1], q2 = q4[2], q3 = q4[3];
    float qn2 = q0.x * q0.x + q0.y * q0.y + q0.z * q0.z + q0.w * q0.w
              + q1.x * q1.x + q1.y * q1.y + q1.z * q1.z + q1.w * q1.w
              + q2.x * q2.x + q2.y * q2.y + q2.z * q2.z + q2.w * q2.w
              + q3.x * q3.x + q3.y * q3.y + q3.z * q3.z + q3.w * q3.w;
    float M = sqrtf(qn2) * kb * fabsf(scale);   // >= max_j |logit| (k pre-scaled)

    u64 qp[8] = { pk(q0.x, q0.y), pk(q0.z, q0.w), pk(q1.x, q1.y), pk(q1.z, q1.w),
                  pk(q2.x, q2.y), pk(q2.z, q2.w), pk(q3.x, q3.y), pk(q3.z, q3.w) };
    u64 acc[8];
#pragma unroll
    for (int d = 0; d < 8; d++) acc[d] = pk1(0.f);
    float s = 0.f;
    const u64 zero = pk1(0.f);

    const ulonglong2* ktU = (const ulonglong2*)ktS;
    const ulonglong2* gtU = (const ulonglong2*)gtS;

    int ntiles = jc >> 8;
    for (int jt = 0; jt < ntiles; jt++) {
        int base = jbeg + (jt << 8);
        __syncthreads();
        for (int i = t; i < 1024; i += 256) {
            int j = i >> 2, c = i & 3;
            ktS[j * 5 + c] = ((const float4*)d_k)[base * 4 + i];
            gtS[j * 5 + c] = ((const float4*)d_g)[base * 4 + i];
        }
        __syncthreads();
#pragma unroll 4
        for (int jj = part; jj < 256; jj += 16) {
            ulonglong2 k0 = ktU[jj * 5], k1 = ktU[jj * 5 + 1], k2 = ktU[jj * 5 + 2], k3 = ktU[jj * 5 + 3];
            u64 dA = fma2(qp[0], k0.x, zero);
            u64 dB = fma2(qp[1], k0.y, zero);
            dA = fma2(qp[2], k1.x, dA);
            dB = fma2(qp[3], k1.y, dB);
            dA = fma2(qp[4], k2.x, dA);
            dB = fma2(qp[5], k2.y, dB);
            dA = fma2(qp[6], k3.x, dA);
            dB = fma2(qp[7], k3.y, dB);
            u64 d2 = add2(dA, dB);
            float2 dd = up2(d2);
            float pe = __expf(dd.x + dd.y - M);
            s += pe;
            u64 pe2 = pk1(pe);
            ulonglong2 g0 = gtU[jj * 5], g1 = gtU[jj * 5 + 1], g2 = gtU[jj * 5 + 2], g3 = gtU[jj * 5 + 3];
            acc[0] = fma2(pe2, g0.x, acc[0]);
            acc[1] = fma2(pe2, g0.y, acc[1]);
            acc[2] = fma2(pe2, g1.x, acc[2]);
            acc[3] = fma2(pe2, g1.y, acc[3]);
            acc[4] = fma2(pe2, g2.x, acc[4]);
            acc[5] = fma2(pe2, g2.y, acc[5]);
            acc[6] = fma2(pe2, g3.x, acc[6]);
            acc[7] = fma2(pe2, g3.y, acc[7]);
        }
    }
    // butterfly reduce across 16 parts (lane bits 0..3)
#pragma unroll
    for (int off = 1; off < 16; off <<= 1) {
        s += __shfl_xor_sync(0xffffffffu, s, off);
#pragma unroll
        for (int d = 0; d < 8; d++)
            acc[d] = add2(acc[d], __shfl_xor_sync(0xffffffffu, acc[d], off));
    }
    if (part == 0 && row0 < B) {
        int pidx = row * 8 + chunk;
        d_ps[pidx] = s;
        float4* dst = (float4*)(d_pacc + pidx * 16);
#pragma unroll
        for (int kq = 0; kq < 4; kq++) {
            float2 a = up2(acc[2 * kq]), bq = up2(acc[2 * kq + 1]);
            dst[kq] = make_float4(a.x, a.y, bq.x, bq.y);
        }
    }
}

// ---------------- head: combine chunk partials, normalize, reduce+cls ----------------
__global__ void __launch_bounds__(256) k_head(
    const float* __restrict__ rw, const float* __restrict__ rb,
    const float* __restrict__ cw, const float* __restrict__ cb, int B)
{
    int row = blockIdx.x * 256 + threadIdx.x;
    if (row >= B) return;
    float s = 0.f;
    float acc[16];
#pragma unroll
    for (int d = 0; d < 16; d++) acc[d] = 0.f;
#pragma unroll
    for (int c = 0; c < 8; c++) {
        int pidx = row * 8 + c;
        s += d_ps[pidx];
        const float4* pa = (const float4*)(d_pacc + pidx * 16);
#pragma unroll
        for (int kq = 0; kq < 4; kq++) {
            float4 v = pa[kq];
            acc[4 * kq + 0] += v.x; acc[4 * kq + 1] += v.y;
            acc[4 * kq + 2] += v.z; acc[4 * kq + 3] += v.w;
        }
    }
    float inv = 1.f / s;
    float r0 = rb[0], r1 = rb[1];
    const float* gp = d_g + row * 16;
#pragma unroll
    for (int d = 0; d < 16; d++) {
        float gv = gp[d];
        float av = acc[d] * inv;
        r0 += gv * rw[d] + av * rw[16 + d];
        r1 += gv * rw[32 + d] + av * rw[48 + d];
    }
    d_outpre[row * 2 + 0] = cb[0] + r0 * cw[0] + r1 * cw[1];
    d_outpre[row * 2 + 1] = cb[1] + r0 * cw[2] + r1 * cw[3];
}

// ---------------- batchnorm ----------------
__global__ void __launch_bounds__(256) k_bn(const float* __restrict__ gamma,
                                            const float* __restrict__ beta,
                                            float* __restrict__ out, int B) {
    __shared__ float sh[1024];
    __shared__ float abv[4];
    int t = threadIdx.x;
    float s0 = 0.f, s1 = 0.f, q0 = 0.f, q1 = 0.f;
    for (int i = t; i < B; i += 256) {
        float2 v = ((const float2*)d_outpre)[i];
        s0 += v.x; q0 += v.x * v.x; s1 += v.y; q1 += v.y * v.y;
    }
    sh[t] = s0; sh[256 + t] = s1; sh[512 + t] = q0; sh[768 + t] = q1;
    __syncthreads();
    for (int off = 128; off; off >>= 1) {
        if (t < off) {
            sh[t] += sh[t + off];
            sh[256 + t] += sh[256 + t + off];
            sh[512 + t] += sh[512 + t + off];
            sh[768 + t] += sh[768 + t + off];
        }
        __syncthreads();
    }
    if (t == 0) {
        float invB = 1.f / (float)B;
        float mu0 = sh[0] * invB, mu1 = sh[256] * invB;
        float v0 = sh[512] * invB - mu0 * mu0;
        float v1 = sh[768] * invB - mu1 * mu1;
        float A0 = gamma[0] * rsqrtf(v0 + 1e-5f);
        float A1 = gamma[1] * rsqrtf(v1 + 1e-5f);
        abv[0] = A0; abv[1] = A1;
        abv[2] = beta[0] - mu0 * A0;
        abv[3] = beta[1] - mu1 * A1;
    }
    __syncthreads();
    int idx = blockIdx.x * 256 + t;
    if (idx < 2 * B) {
        int ch = idx & 1;
        out[idx] = d_outpre[idx] * abv[ch] + abv[2 + ch];
    }
}

// ---------------- launch ----------------
extern "C" void kernel_launch(void* const* d_in, const int* in_sizes, int n_in,
                              void* d_out, int out_size) {
    const float* x   = (const float*)d_in[0];
    const float* c1w = (const float*)d_in[1];
    const float* c1b = (const float*)d_in[2];
    const float* c2w = (const float*)d_in[3];
    const float* c2b = (const float*)d_in[4];
    const float* c3w = (const float*)d_in[5];
    const float* c3b = (const float*)d_in[6];
    const float* g1  = (const float*)d_in[7];
    const float* g2  = (const float*)d_in[8];
    const float* rot = (const float*)d_in[9];
    const float* ent = (const float*)d_in[10];
    const float* rw  = (const float*)d_in[11];
    const float* rb  = (const float*)d_in[12];
    const float* cw  = (const float*)d_in[13];
    const float* cb  = (const float*)d_in[14];
    const float* gam = (const float*)d_in[15];
    const float* bet = (const float*)d_in[16];

    int B = in_sizes[0] / 1024;

    cudaFuncSetAttribute(k_feat, cudaFuncAttributeMaxDynamicSharedMemorySize, SM_BYTES);

    k_feat<<<B, 256, SM_BYTES>>>(x, c1w, c1b, c2w, c2b, c3w, c3b, g1, g2, rot, ent);
    k_attn<<<(B / 16) * 8, 256>>>(rot, ent, B);
    k_head<<<(B + 255) / 256, 256>>>(rw, rb, cw, cb, B);
    k_bn<<<(2 * B + 255) / 256, 256>>>(gam, bet, (float*)d_out, B);
}

// round 17
// speedup vs baseline: 1.0303x; 1.0303x over previous
#include <cuda_runtime.h>
#include <stdint.h>
#include <math.h>

// ---------------- scratch ----------------
#define BMAX 4096
__device__ __align__(16) float d_g[BMAX * 16];
__device__ __align__(16) float d_q[BMAX * 16];
__device__ __align__(16) float d_k[BMAX * 16];   // pre-scaled by softmax scale
__device__ __align__(16) float d_outpre[BMAX * 2];
__device__ __align__(16) float d_ps[BMAX * 8];        // partial softmax denominators
__device__ __align__(16) float d_pacc[BMAX * 8 * 16]; // partial numerators

// ---------------- packed f32x2 helpers ----------------
typedef unsigned long long u64;
typedef unsigned int u32;
__device__ __forceinline__ u64 pk(float lo, float hi) {
    u64 r; asm("mov.b64 %0, {%1,%2};" : "=l"(r) : "f"(lo), "f"(hi)); return r;
}
__device__ __forceinline__ u64 pk1(float v) { return pk(v, v); }
__device__ __forceinline__ u64 fma2(u64 a, u64 b, u64 c) {
    u64 d; asm("fma.rn.f32x2 %0, %1, %2, %3;" : "=l"(d) : "l"(a), "l"(b), "l"(c)); return d;
}
__device__ __forceinline__ u64 add2(u64 a, u64 b) {
    u64 d; asm("add.rn.f32x2 %0, %1, %2;" : "=l"(d) : "l"(a), "l"(b)); return d;
}
__device__ __forceinline__ float2 up2(u64 v) {
    float2 f; asm("mov.b64 {%0,%1}, %2;" : "=f"(f.x), "=f"(f.y) : "l"(v)); return f;
}
__device__ __forceinline__ void cpasync16(u32 saddr, const void* gaddr) {
    asm volatile("cp.async.ca.shared.global [%0], [%1], 16;" :: "r"(saddr), "l"(gaddr) : "memory");
}

// ---------------- fused feature kernel smem layout (floats) — R11 layout ----------------
#define O_WC1   0
#define O_BS1   96
#define O_WC2   104
#define O_BS2   1640
#define O_WC3   1656
#define O_BS3   7800
#define O_A     7832
#define O_IMG   O_A
#define O_H2    O_A
#define O_H1    9752
#define O_W1    9752
#define O_W2    10808
#define O_R     11336
#define O_FEAT  11352
#define O_AVEC  11384
#define O_GVEC  11416
#define SM_FLOATS 12632
#define SM_BYTES  (SM_FLOATS * 4)

__global__ void __launch_bounds__(256) k_feat(
    const float* __restrict__ x,
    const float* __restrict__ c1w, const float* __restrict__ c1b,
    const float* __restrict__ c2w, const float* __restrict__ c2b,
    const float* __restrict__ c3w, const float* __restrict__ c3b,
    const float* __restrict__ w1, const float* __restrict__ w2,
    const float* __restrict__ R, const float* __restrict__ ent)
{
    extern __shared__ __align__(16) float sm[];
    float* wc1 = sm + O_WC1;  float* bs1 = sm + O_BS1;
    float* wc2 = sm + O_WC2;  float* bs2 = sm + O_BS2;
    float* wc3 = sm + O_WC3;  float* bs3 = sm + O_BS3;
    float* img = sm + O_IMG;  float* h1 = sm + O_H1;  float* h2 = sm + O_H2;

    int b = blockIdx.x, t = threadIdx.x;

    {
        float4 z = make_float4(0.f, 0.f, 0.f, 0.f);
        float4* p1 = (float4*)img;
        float4* p2 = (float4*)h1;
        for (int i = t; i < 306; i += 256) p1[i] = z;
        for (int i = t; i < 720; i += 256) p2[i] = z;
    }
    for (int i = t; i < 72; i += 256)   { int g = i / 9, zz = i - g * 9; wc1[g * 12 + zz] = c1w[i]; }
    if (t < 8)  bs1[t] = c1b[t];
    for (int i = t; i < 1152; i += 256) { int g = i / 9, zz = i - g * 9; wc2[g * 12 + zz] = c2w[i]; }
    if (t < 16) bs2[t] = c2b[t];
    for (int i = t; i < 4608; i += 256) { int g = i / 9, zz = i - g * 9; wc3[g * 12 + zz] = c3w[i]; }
    if (t < 32) bs3[t] = c3b[t];
    __syncthreads();

    {
        float4 v = ((const float4*)x)[b * 256 + t];
        int r = t >> 3, c = (t & 7) * 4;
        float* dst = img + (r + 1) * 36 + c + 1;
        dst[0] = v.x; dst[1] = v.y; dst[2] = v.z; dst[3] = v.w;
    }
    __syncthreads();

    // ---- conv1 ----
    {
        int ph = t >> 4, pw = t & 15;
        const float* ip = img + 2 * ph * 36 + 2 * pw;
        u64 pr[4][3];
#pragma unroll
        for (int yy = 0; yy < 4; yy++) {
            float2 e01 = *(const float2*)(ip + yy * 36);
            float2 e23 = *(const float2*)(ip + yy * 36 + 2);
            pr[yy][0] = pk(e01.x, e01.y);
            pr[yy][1] = pk(e01.y, e23.x);
            pr[yy][2] = pk(e23.x, e23.y);
        }
#pragma unroll
        for (int c = 0; c < 8; c++) {
            const float4* wp4 = (const float4*)(wc1 + c * 12);
            float4 wa = wp4[0], wb = wp4[1];
            float w8 = ((const float*)wp4)[8];
            float wv[9] = { wa.x, wa.y, wa.z, wa.w, wb.x, wb.y, wb.z, wb.w, w8 };
            u64 aA = pk1(bs1[c]), aB = aA;
#pragma unroll
            for (int ky = 0; ky < 3; ky++)
#pragma unroll
                for (int kx = 0; kx < 3; kx++) {
                    u64 w2v = pk1(wv[ky * 3 + kx]);
                    aA = fma2(pr[ky][kx], w2v, aA);
                    aB = fma2(pr[ky + 1][kx], w2v, aB);
                }
            float2 A = up2(aA), Bv = up2(aB);
            float m = fmaxf(fmaxf(fmaxf(A.x, A.y), fmaxf(Bv.x, Bv.y)), 0.f);
            h1[c * 360 + (ph + 1) * 20 + (pw + 1)] = m;
        }
    }
    __syncthreads();

    {
        float4 z = make_float4(0.f, 0.f, 0.f, 0.f);
        float4* p3 = (float4*)h2;
        for (int i = t; i < 480; i += 256) p3[i] = z;
    }
    __syncthreads();

    // ---- conv2 ----
    {
        int c0 = t >> 6, pos = t & 63, ph = pos >> 3, pw = pos & 7;
        u64 accA[4], accB[4];
#pragma unroll
        for (int oo = 0; oo < 4; oo++) { accA[oo] = pk1(bs2[c0 + 4 * oo]); accB[oo] = accA[oo]; }
#pragma unroll 1
        for (int ic = 0; ic < 8; ic++) {
            const float* hp = h1 + ic * 360 + 2 * ph * 20 + 2 * pw;
            u64 pr[4][3];
#pragma unroll
            for (int yy = 0; yy < 4; yy++) {
                float2 e01 = *(const float2*)(hp + yy * 20);
                float2 e23 = *(const float2*)(hp + yy * 20 + 2);
                pr[yy][0] = pk(e01.x, e01.y);
                pr[yy][1] = pk(e01.y, e23.x);
                pr[yy][2] = pk(e23.x, e23.y);
            }
#pragma unroll
            for (int oo = 0; oo < 4; oo++) {
                const float4* wp4 = (const float4*)(wc2 + ((c0 + 4 * oo) * 8 + ic) * 12);
                float4 wa = wp4[0], wb = wp4[1];
                float w8 = ((const float*)wp4)[8];
                float wv[9] = { wa.x, wa.y, wa.z, wa.w, wb.x, wb.y, wb.z, wb.w, w8 };
#pragma unroll
                for (int ky = 0; ky < 3; ky++)
#pragma unroll
                    for (int kx = 0; kx < 3; kx++) {
                        u64 w2v = pk1(wv[ky * 3 + kx]);
                        accA[oo] = fma2(pr[ky][kx], w2v, accA[oo]);
                        accB[oo] = fma2(pr[ky + 1][kx], w2v, accB[oo]);
                    }
            }
        }
#pragma unroll
        for (int oo = 0; oo < 4; oo++) {
            float2 A = up2(accA[oo]), Bv = up2(accB[oo]);
            float m = fmaxf(fmaxf(fmaxf(A.x, A.y), fmaxf(Bv.x, Bv.y)), 0.f);
            h2[(c0 + 4 * oo) * 120 + (ph + 1) * 12 + (pw + 1)] = m;
        }
    }
    __syncthreads();

    // ---- conv3 + mean; stage gnn weights into dead h1 region ----
    float* w1s = sm + O_W1; float* w2s = sm + O_W2; float* Rs = sm + O_R;
    float* feats = sm + O_FEAT; float* avec = sm + O_AVEC; float* gvec = sm + O_GVEC;
    for (int i = t; i < 1024; i += 256) w1s[(i >> 5) * 33 + (i & 31)] = w1[i];
    for (int i = t; i < 512; i += 256)  w2s[(i >> 5) * 33 + (i & 31)] = w2[i];
    if (t < 16) Rs[t] = R[t];
    {
        int oc = t >> 3, oy = t & 7;
        u64 acc[4];
#pragma unroll
        for (int m = 0; m < 4; m++) acc[m] = pk1(bs3[oc]);
#pragma unroll 1
        for (int ic = 0; ic < 16; ic++) {
            const float4* rp = (const float4*)(h2 + ic * 120 + oy * 12);
            const float4* wp4 = (const float4*)(wc3 + (oc * 16 + ic) * 12);
            float4 wa = wp4[0], wb = wp4[1];
            float w8 = ((const float*)wp4)[8];
            float wv[9] = { wa.x, wa.y, wa.z, wa.w, wb.x, wb.y, wb.z, wb.w, w8 };
#pragma unroll
            for (int ky = 0; ky < 3; ky++) {
                float4 ra = rp[ky * 3], rb = rp[ky * 3 + 1], rc = rp[ky * 3 + 2];
                u64 pr[9];
                pr[0] = pk(ra.x, ra.y); pr[1] = pk(ra.y, ra.z); pr[2] = pk(ra.z, ra.w);
                pr[3] = pk(ra.w, rb.x);
                pr[4] = pk(rb.x, rb.y); pr[5] = pk(rb.y, rb.z); pr[6] = pk(rb.z, rb.w);
                pr[7] = pk(rb.w, rc.x);
                pr[8] = pk(rc.x, rc.y);
#pragma unroll
                for (int kx = 0; kx < 3; kx++) {
                    u64 w2v = pk1(wv[ky * 3 + kx]);
                    acc[0] = fma2(pr[kx], w2v, acc[0]);
                    acc[1] = fma2(pr[2 + kx], w2v, acc[1]);
                    acc[2] = fma2(pr[4 + kx], w2v, acc[2]);
                    acc[3] = fma2(pr[6 + kx], w2v, acc[3]);
                }
            }
        }
        float s = 0.f;
#pragma unroll
        for (int m = 0; m < 4; m++) {
            float2 v = up2(acc[m]);
            s += fmaxf(v.x, 0.f) + fmaxf(v.y, 0.f);
        }
        int sub = t & 7;
#pragma unroll
        for (int off = 4; off; off >>= 1) {
            float o = __shfl_down_sync(0xffffffffu, s, off, 8);
            if (sub + off < 8) s += o;
        }
        if (sub == 0) feats[oc] = s * (1.f / 64.f);
    }
    __syncthreads();

    // ---- gnn on warp 0 ----
    if (t < 32) {
        float a = 0.f;
#pragma unroll
        for (int i = 0; i < 32; i++) a += feats[i] * w1s[t * 33 + i];
        avec[t] = tanhf(a);
        __syncwarp();
        if (t < 16) {
            float g = 0.f;
#pragma unroll
            for (int i = 0; i < 32; i++) g += avec[i] * w2s[t * 33 + i];
            g = tanhf(g);
            gvec[t] = g;
            d_g[b * 16 + t] = g;
        }
        __syncwarp();
        if (t < 16) {
            float scale = (cosf(ent[0]) + cosf(ent[1]) + cosf(ent[2])) * (1.f / 3.f) * 0.25f;
            int r = t >> 2, cc = t & 3;
            float qv = 0.f, kv = 0.f;
#pragma unroll
            for (int m = 0; m < 4; m++) {
                float gm = gvec[r * 4 + m];
                qv += gm * Rs[m * 4 + cc];
                kv += gm * Rs[cc * 4 + m];
            }
            d_q[b * 16 + t] = qv;
            d_k[b * 16 + t] = kv * scale;
        }
    }
}

// ---------------- attention partials: 16 rows x B/8 j-chunk, double-buffered cp.async tiles ----------------
// 128-row tiles, 2 buffers (same smem footprint); tile jt+1 loads overlap tile jt compute.
__global__ void __launch_bounds__(256) k_attn(
    const float* __restrict__ R, const float* __restrict__ ent, int B)
{
    __shared__ __align__(16) float4 ktS[2][128 * 5];
    __shared__ __align__(16) float4 gtS[2][128 * 5];
    int t = threadIdx.x;
    int r = t >> 4, part = t & 15;
    int rb = blockIdx.x >> 3;
    int chunk = blockIdx.x & 7;
    int row0 = rb * 16 + r;
    int row = min(row0, B - 1);
    int jc = B >> 3;
    int jbeg = chunk * jc;

    float temp = (cosf(ent[0]) + cosf(ent[1]) + cosf(ent[2])) * (1.f / 3.f);
    float scale = temp * 0.25f;
    float sum2 = 0.f;
#pragma unroll
    for (int c = 0; c < 4; c++) {
        float rs = fabsf(R[c * 4]) + fabsf(R[c * 4 + 1]) + fabsf(R[c * 4 + 2]) + fabsf(R[c * 4 + 3]);
        sum2 += rs * rs;
    }
    float kb = 2.f * sqrtf(sum2);

    const float4* q4 = (const float4*)d_q + row * 4;
    float4 q0 = q4[0], q1 = q4[1], q2 = q4[2], q3 = q4[3];
    float qn2 = q0.x * q0.x + q0.y * q0.y + q0.z * q0.z + q0.w * q0.w
              + q1.x * q1.x + q1.y * q1.y + q1.z * q1.z + q1.w * q1.w
              + q2.x * q2.x + q2.y * q2.y + q2.z * q2.z + q2.w * q2.w
              + q3.x * q3.x + q3.y * q3.y + q3.z * q3.z + q3.w * q3.w;
    float M = sqrtf(qn2) * kb * fabsf(scale);   // >= max_j |logit| (k pre-scaled)

    u64 qp[8] = { pk(q0.x, q0.y), pk(q0.z, q0.w), pk(q1.x, q1.y), pk(q1.z, q1.w),
                  pk(q2.x, q2.y), pk(q2.z, q2.w), pk(q3.x, q3.y), pk(q3.z, q3.w) };
    u64 acc[8];
#pragma unroll
    for (int d = 0; d < 8; d++) acc[d] = pk1(0.f);
    float s = 0.f;
    const u64 zero = pk1(0.f);

    // prefetch indices: each thread covers float4 index t and t+256 of 512 per array
    int j0 = t >> 2, c0i = t & 3;
    int j1 = (t + 256) >> 2;            // (t+256)&3 == t&3
    u32 skt0 = (u32)__cvta_generic_to_shared(&ktS[0][j0 * 5 + c0i]);
    u32 sgt0 = (u32)__cvta_generic_to_shared(&gtS[0][j0 * 5 + c0i]);
    u32 skt1 = (u32)__cvta_generic_to_shared(&ktS[0][j1 * 5 + c0i]);
    u32 sgt1 = (u32)__cvta_generic_to_shared(&gtS[0][j1 * 5 + c0i]);
    const u32 bufstride = (u32)(128 * 5 * sizeof(float4));

    int ntiles = jc >> 7;

    // prefetch tile 0 into buffer 0
    {
        int base = jbeg;
        cpasync16(skt0, (const float4*)d_k + (base + j0) * 4 + c0i);
        cpasync16(sgt0, (const float4*)d_g + (base + j0) * 4 + c0i);
        cpasync16(skt1, (const float4*)d_k + (base + j1) * 4 + c0i);
        cpasync16(sgt1, (const float4*)d_g + (base + j1) * 4 + c0i);
        asm volatile("cp.async.commit_group;" ::: "memory");
    }

    for (int jt = 0; jt < ntiles; jt++) {
        int cur = jt & 1;
        if (jt + 1 < ntiles) {
            u32 off = (cur ^ 1) ? bufstride : 0u;
            int base = jbeg + ((jt + 1) << 7);
            cpasync16(skt0 + off, (const float4*)d_k + (base + j0) * 4 + c0i);
            cpasync16(sgt0 + off, (const float4*)d_g + (base + j0) * 4 + c0i);
            cpasync16(skt1 + off, (const float4*)d_k + (base + j1) * 4 + c0i);
            cpasync16(sgt1 + off, (const float4*)d_g + (base + j1) * 4 + c0i);
            asm volatile("cp.async.commit_group;" ::: "memory");
            asm volatile("cp.async.wait_group 1;" ::: "memory");
        } else {
            asm volatile("cp.async.wait_group 0;" ::: "memory");
        }
        __syncthreads();
        const ulonglong2* ktU = (const ulonglong2*)ktS[cur];
        const ulonglong2* gtU = (const ulonglong2*)gtS[cur];
#pragma unroll 4
        for (int jj = part; jj < 128; jj += 16) {
            ulonglong2 k0 = ktU[jj * 5], k1 = ktU[jj * 5 + 1], k2 = ktU[jj * 5 + 2], k3 = ktU[jj * 5 + 3];
            u64 dA = fma2(qp[0], k0.x, zero);
            u64 dB = fma2(qp[1], k0.y, zero);
            dA = fma2(qp[2], k1.x, dA);
            dB = fma2(qp[3], k1.y, dB);
            dA = fma2(qp[4], k2.x, dA);
            dB = fma2(qp[5], k2.y, dB);
            dA = fma2(qp[6], k3.x, dA);
            dB = fma2(qp[7], k3.y, dB);
            u64 d2 = add2(dA, dB);
            float2 dd = up2(d2);
            float pe = __expf(dd.x + dd.y - M);
            s += pe;
            u64 pe2 = pk1(pe);
            ulonglong2 g0 = gtU[jj * 5], g1 = gtU[jj * 5 + 1], g2 = gtU[jj * 5 + 2], g3 = gtU[jj * 5 + 3];
            acc[0] = fma2(pe2, g0.x, acc[0]);
            acc[1] = fma2(pe2, g0.y, acc[1]);
            acc[2] = fma2(pe2, g1.x, acc[2]);
            acc[3] = fma2(pe2, g1.y, acc[3]);
            acc[4] = fma2(pe2, g2.x, acc[4]);
            acc[5] = fma2(pe2, g2.y, acc[5]);
            acc[6] = fma2(pe2, g3.x, acc[6]);
            acc[7] = fma2(pe2, g3.y, acc[7]);
        }
        __syncthreads();
    }
    // butterfly reduce across 16 parts (lane bits 0..3)
#pragma unroll
    for (int off = 1; off < 16; off <<= 1) {
        s += __shfl_xor_sync(0xffffffffu, s, off);
#pragma unroll
        for (int d = 0; d < 8; d++)
            acc[d] = add2(acc[d], __shfl_xor_sync(0xffffffffu, acc[d], off));
    }
    if (part == 0 && row0 < B) {
        int pidx = row * 8 + chunk;
        d_ps[pidx] = s;
        float4* dst = (float4*)(d_pacc + pidx * 16);
#pragma unroll
        for (int kq = 0; kq < 4; kq++) {
            float2 a = up2(acc[2 * kq]), bq = up2(acc[2 * kq + 1]);
            dst[kq] = make_float4(a.x, a.y, bq.x, bq.y);
        }
    }
}

// ---------------- head: combine chunk partials, normalize, reduce+cls ----------------
__global__ void __launch_bounds__(256) k_head(
    const float* __restrict__ rw, const float* __restrict__ rb,
    const float* __restrict__ cw, const float* __restrict__ cb, int B)
{
    int row = blockIdx.x * 256 + threadIdx.x;
    if (row >= B) return;
    float s = 0.f;
    float acc[16];
#pragma unroll
    for (int d = 0; d < 16; d++) acc[d] = 0.f;
#pragma unroll
    for (int c = 0; c < 8; c++) {
        int pidx = row * 8 + c;
        s += d_ps[pidx];
        const float4* pa = (const float4*)(d_pacc + pidx * 16);
#pragma unroll
        for (int kq = 0; kq < 4; kq++) {
            float4 v = pa[kq];
            acc[4 * kq + 0] += v.x; acc[4 * kq + 1] += v.y;
            acc[4 * kq + 2] += v.z; acc[4 * kq + 3] += v.w;
        }
    }
    float inv = 1.f / s;
    float r0 = rb[0], r1 = rb[1];
    const float* gp = d_g + row * 16;
#pragma unroll
    for (int d = 0; d < 16; d++) {
        float gv = gp[d];
        float av = acc[d] * inv;
        r0 += gv * rw[d] + av * rw[16 + d];
        r1 += gv * rw[32 + d] + av * rw[48 + d];
    }
    d_outpre[row * 2 + 0] = cb[0] + r0 * cw[0] + r1 * cw[1];
    d_outpre[row * 2 + 1] = cb[1] + r0 * cw[2] + r1 * cw[3];
}

// ---------------- batchnorm ----------------
__global__ void __launch_bounds__(256) k_bn(const float* __restrict__ gamma,
                                            const float* __restrict__ beta,
                                            float* __restrict__ out, int B) {
    __shared__ float sh[1024];
    __shared__ float abv[4];
    int t = threadIdx.x;
    float s0 = 0.f, s1 = 0.f, q0 = 0.f, q1 = 0.f;
    for (int i = t; i < B; i += 256) {
        float2 v = ((const float2*)d_outpre)[i];
        s0 += v.x; q0 += v.x * v.x; s1 += v.y; q1 += v.y * v.y;
    }
    sh[t] = s0; sh[256 + t] = s1; sh[512 + t] = q0; sh[768 + t] = q1;
    __syncthreads();
    for (int off = 128; off; off >>= 1) {
        if (t < off) {
            sh[t] += sh[t + off];
            sh[256 + t] += sh[256 + t + off];
            sh[512 + t] += sh[512 + t + off];
            sh[768 + t] += sh[768 + t + off];
        }
        __syncthreads();
    }
    if (t == 0) {
        float invB = 1.f / (float)B;
        float mu0 = sh[0] * invB, mu1 = sh[256] * invB;
        float v0 = sh[512] * invB - mu0 * mu0;
        float v1 = sh[768] * invB - mu1 * mu1;
        float A0 = gamma[0] * rsqrtf(v0 + 1e-5f);
        float A1 = gamma[1] * rsqrtf(v1 + 1e-5f);
        abv[0] = A0; abv[1] = A1;
        abv[2] = beta[0] - mu0 * A0;
        abv[3] = beta[1] - mu1 * A1;
    }
    __syncthreads();
    int idx = blockIdx.x * 256 + t;
    if (idx < 2 * B) {
        int ch = idx & 1;
        out[idx] = d_outpre[idx] * abv[ch] + abv[2 + ch];
    }
}

// ---------------- launch ----------------
extern "C" void kernel_launch(void* const* d_in, const int* in_sizes, int n_in,
                              void* d_out, int out_size) {
    const float* x   = (const float*)d_in[0];
    const float* c1w = (const float*)d_in[1];
    const float* c1b = (const float*)d_in[2];
    const float* c2w = (const float*)d_in[3];
    const float* c2b = (const float*)d_in[4];
    const float* c3w = (const float*)d_in[5];
    const float* c3b = (const float*)d_in[6];
    const float* g1  = (const float*)d_in[7];
    const float* g2  = (const float*)d_in[8];
    const float* rot = (const float*)d_in[9];
    const float* ent = (const float*)d_in[10];
    const float* rw  = (const float*)d_in[11];
    const float* rb  = (const float*)d_in[12];
    const float* cw  = (const float*)d_in[13];
    const float* cb  = (const float*)d_in[14];
    const float* gam = (const float*)d_in[15];
    const float* bet = (const float*)d_in[16];

    int B = in_sizes[0] / 1024;

    cudaFuncSetAttribute(k_feat, cudaFuncAttributeMaxDynamicSharedMemorySize, SM_BYTES);

    k_feat<<<B, 256, SM_BYTES>>>(x, c1w, c1b, c2w, c2b, c3w, c3b, g1, g2, rot, ent);
    k_attn<<<(B / 16) * 8, 256>>>(rot, ent, B);
    k_head<<<(B + 255) / 256, 256>>>(rw, rb, cw, cb, B);
    k_bn<<<(2 * B + 255) / 256, 256>>>(gam, bet, (float*)d_out, B);
}